// round 10
// baseline (speedup 1.0000x reference)
#include <cuda_runtime.h>
#include <cstdint>

#define KB    8192           // bins (bin = S>>1, S = round(v*2^14) in [0,16383])
#define NCH   16             // scan chunks per batch (512 bins each)
#define BF4   65536          // float4 per stream per batch (HW/4), = 1<<16
#define HW    262144
#define MAXB  64
#define MAXG  512            // max grid (2*SMs)
#define TPB   1024

// scratch (allocation-free rule: __device__ globals; zero-initialized)
__device__ unsigned int       g_part[MAXG * 2 * KB];   // per-CTA 2-half packed hists
__device__ int                g_csum[MAXG * 32];       // per-CTA [half][chunk] d sums
__device__ unsigned long long g_accum;                 // exact integer total
__device__ int                g_done;                  // finished scan-CTA counter

// packed word: T = d*2^22 + S,  S = sum(+-round(v*2^14)) clamped to [0,16383]
__device__ __forceinline__ int decD(unsigned int t) {
    return ((int)t + (1 << 21)) >> 22;
}
__device__ __forceinline__ unsigned int quantS(float v) {
    int S = __float2int_rn(v * 16384.0f);
    return (unsigned int)min(S, 16383);
}

// ---------------------------------------------------------------------------
// K1: equal-work chunks across the whole [B*HW] stream; each CTA keeps two
// 8192-bin signed packed histograms (its chunk spans at most 2 batches).
// grid = G = 2*numSM, block = 1024, dynamic smem = 64 KB.
// ---------------------------------------------------------------------------
__global__ void __launch_bounds__(TPB, 2) k_hist(const float* __restrict__ x,
                                                 const float* __restrict__ y,
                                                 int G, int NF4) {
    extern __shared__ unsigned int sh[];   // [2*KB]
    __shared__ int sc[32];
    int cta = blockIdx.x;
    int t = threadIdx.x, lane = t & 31;

    uint4* s4 = (uint4*)sh;
#pragma unroll
    for (int j = 0; j < 4; ++j) s4[t + j * TPB] = make_uint4(0u, 0u, 0u, 0u);
    if (t < 32) sc[t] = 0;
    __syncthreads();

    int i0 = (int)(((long long)cta * NF4) / G);
    int i1 = (int)(((long long)(cta + 1) * NF4) / G);
    int bfirst = i0 >> 16;
    int ibreak = (bfirst + 1) << 16;       // first float4 index of next batch
    if (ibreak > i1) ibreak = i1;

    const float4* px = (const float4*)x;
    const float4* py = (const float4*)y;
    for (int i = i0 + t; i < i1; i += TPB) {
        unsigned int off = (i >= ibreak) ? KB : 0u;
        float4 vx = px[i];
        float4 vy = py[i];
        unsigned int s;
        s = quantS(vx.x); atomicAdd(&sh[off + (s >> 1)], (1u << 22) + s);
        s = quantS(vy.x); atomicAdd(&sh[off + (s >> 1)], (unsigned int)(-(int)((1u << 22) + s)));
        s = quantS(vx.y); atomicAdd(&sh[off + (s >> 1)], (1u << 22) + s);
        s = quantS(vy.y); atomicAdd(&sh[off + (s >> 1)], (unsigned int)(-(int)((1u << 22) + s)));
        s = quantS(vx.z); atomicAdd(&sh[off + (s >> 1)], (1u << 22) + s);
        s = quantS(vy.z); atomicAdd(&sh[off + (s >> 1)], (unsigned int)(-(int)((1u << 22) + s)));
        s = quantS(vx.w); atomicAdd(&sh[off + (s >> 1)], (1u << 22) + s);
        s = quantS(vy.w); atomicAdd(&sh[off + (s >> 1)], (unsigned int)(-(int)((1u << 22) + s)));
    }
    __syncthreads();

    // write-out both halves (coalesced uint4) + per-(half,chunk) d sums.
    // uint4 idx 0..4095: half*16+chunk = idx>>7; warp never crosses chunks.
    unsigned int* g = g_part + (size_t)cta * (2 * KB);
#pragma unroll
    for (int j = 0; j < 4; ++j) {
        int idx = t + j * TPB;
        uint4 v = s4[idx];
        ((uint4*)g)[idx] = v;
        int d = decD(v.x) + decD(v.y) + decD(v.z) + decD(v.w);
#pragma unroll
        for (int o = 16; o; o >>= 1) d += __shfl_down_sync(0xffffffffu, d, o);
        if (lane == 0 && d != 0) atomicAdd(&sc[idx >> 7], d);
    }
    __syncthreads();
    if (t < 32) g_csum[cta * 32 + t] = sc[t];
}

// ---------------------------------------------------------------------------
// K2: per-(batch, chunk) scan. Finds the <=8 contributing (cta, half) pairs,
// sums their partials, applies decoupled carry, exact integer |integral|:
//   2^15 * integ_k = 4*Din + d_k*(4k+3) - 2*S_k
// grid = B*NCH, block = 128 (4 bins/thread).
// ---------------------------------------------------------------------------
__global__ void __launch_bounds__(128) k_scan(float* __restrict__ out,
                                              int B, int G, int NF4) {
    __shared__ int wt[4];
    __shared__ int wc[4];
    __shared__ long long wr[4];

    int cta = blockIdx.x;
    int b = cta >> 4, ch = cta & (NCH - 1);
    int t = threadIdx.x, lane = t & 31, wid = t >> 5;

    // ---- contributing (cta, half) pairs for batch b (uniform per thread) ----
    int jlo = b << 16, jhi = (b + 1) << 16;
    int cA = (int)(((long long)jlo * G) / NF4) - 1;
    int cB = (int)(((long long)(jhi - 1) * G) / NF4) + 1;
    if (cA < 0) cA = 0;
    if (cB > G - 1) cB = G - 1;
    int cList[10], hList[10], nc = 0;
    for (int c = cA; c <= cB; ++c) {
        int ci0 = (int)(((long long)c * NF4) / G);
        int ci1 = (int)(((long long)(c + 1) * NF4) / G);
        if (ci1 > jlo && ci0 < jhi) {
            cList[nc] = c;
            hList[nc] = ((ci0 >> 16) == b) ? 0 : 1;
            ++nc;
        }
    }

    // ---- sum partial hists for my 4 bins ----
    int g0 = ch * 512 + t * 4;
    unsigned int T0 = 0u, T1 = 0u, T2 = 0u, T3 = 0u;
    for (int e = 0; e < nc; ++e) {
        const unsigned int* p =
            g_part + ((size_t)cList[e] * 2 + hList[e]) * KB + g0;
        uint4 a = *(const uint4*)p;
        T0 += a.x; T1 += a.y; T2 += a.z; T3 += a.w;
    }
    int d0 = decD(T0), d1 = decD(T1), d2 = decD(T2), d3 = decD(T3);
    int S0 = (int)T0 - (d0 << 22);
    int S1 = (int)T1 - (d1 << 22);
    int S2 = (int)T2 - (d2 << 22);
    int S3 = (int)T3 - (d3 << 22);
    int tsum = d0 + d1 + d2 + d3;

    // ---- carry = sum over contributors of earlier chunks' d sums ----
    int cpart = 0;
    if (ch > 0) {
        int nvals = nc * ch;
        for (int idx = t; idx < nvals; idx += 128) {
            int e = idx / ch, cj = idx - e * ch;
            cpart += g_csum[cList[e] * 32 + hList[e] * NCH + cj];
        }
    }
#pragma unroll
    for (int o = 16; o; o >>= 1) cpart += __shfl_down_sync(0xffffffffu, cpart, o);
    if (lane == 0) wc[wid] = cpart;

    // ---- block exclusive scan of tsum over 128 threads ----
    int s = tsum;
#pragma unroll
    for (int o = 1; o < 32; o <<= 1) {
        int u = __shfl_up_sync(0xffffffffu, s, o);
        if (lane >= o) s += u;
    }
    if (lane == 31) wt[wid] = s;
    __syncthreads();
    int carry = wc[0] + wc[1] + wc[2] + wc[3];
    int woff = 0;
#pragma unroll
    for (int r = 0; r < 4; ++r) woff += (r < wid) ? wt[r] : 0;
    long long Din = (long long)carry + woff + (s - tsum);

    // ---- exact per-bin |integral| (scaled by 2^15) ----
    long long acc = 0, v;
    v = 4 * Din + (long long)d0 * (4LL * g0 + 3) - 2LL * S0;  acc += v < 0 ? -v : v;  Din += d0;
    v = 4 * Din + (long long)d1 * (4LL * g0 + 7) - 2LL * S1;  acc += v < 0 ? -v : v;  Din += d1;
    v = 4 * Din + (long long)d2 * (4LL * g0 + 11) - 2LL * S2; acc += v < 0 ? -v : v;  Din += d2;
    v = 4 * Din + (long long)d3 * (4LL * g0 + 15) - 2LL * S3; acc += v < 0 ? -v : v;

    // ---- block reduce, accumulate, last scan-CTA writes out ----
#pragma unroll
    for (int o = 16; o; o >>= 1) acc += __shfl_down_sync(0xffffffffu, acc, o);
    if (lane == 0) wr[wid] = acc;
    __syncthreads();
    if (t == 0) {
        acc = wr[0] + wr[1] + wr[2] + wr[3];
        atomicAdd(&g_accum, (unsigned long long)acc);
        __threadfence();
        int r2 = atomicAdd(&g_done, 1);
        if (r2 == B * NCH - 1) {
            unsigned long long tot = atomicAdd(&g_accum, 0ull);
            out[0] = (float)((double)(long long)tot * (1.0 / 32768.0));
            g_accum = 0ull;  // reset for next graph replay
            g_done = 0;
        }
    }
}

extern "C" void kernel_launch(void* const* d_in, const int* in_sizes, int n_in,
                              void* d_out, int out_size) {
    const float* x = (const float*)d_in[0];
    const float* y = (const float*)d_in[1];
    int B = in_sizes[0] / HW;
    if (B > MAXB) B = MAXB;
    int NF4 = B * BF4;

    int sm = 148;
    cudaDeviceGetAttribute(&sm, cudaDevAttrMultiProcessorCount, 0);
    int G = 2 * sm;
    if (G > MAXG) G = MAXG;
    if (G < B) G = B;   // guarantee a chunk spans at most 2 batches

    cudaFuncSetAttribute(k_hist, cudaFuncAttributeMaxDynamicSharedMemorySize,
                         2 * KB * (int)sizeof(unsigned int));

    k_hist<<<G, TPB, 2 * KB * sizeof(unsigned int)>>>(x, y, G, NF4);
    k_scan<<<B * NCH, 128>>>((float*)d_out, B, G, NF4);
}

// round 11
// speedup vs baseline: 1.2917x; 1.2917x over previous
#include <cuda_runtime.h>
#include <cstdint>

#define KB    8192           // bins (bin = S>>1, S = round(v*2^14))
#define SEG   2048           // bins per CTA in phase 2 (KB / CLUSTER)
#define CLU   4              // CTAs per batch = cluster size
#define HW    262144         // H*W per batch
#define MAXB  64
#define TPB   1024

// scratch (allocation-free rule: __device__ globals; zero-initialized)
__device__ unsigned long long g_accum;   // exact integer total
__device__ int                g_done;    // finished-CTA counter

// packed word: T = d*2^22 + S,  S = sum(+-round(v*2^14)) clamped to [0,16383]
__device__ __forceinline__ int decD(unsigned int t) {
    return ((int)t + (1 << 21)) >> 22;
}
__device__ __forceinline__ unsigned int quantS(float v) {
    int S = __float2int_rn(v * 16384.0f);
    return (unsigned int)min(S, 16383);
}

__device__ __forceinline__ uint32_t smem_u32(const void* p) {
    uint32_t a;
    asm("{ .reg .u64 t; cvta.to.shared.u64 t, %1; cvt.u32.u64 %0, t; }" : "=r"(a) : "l"(p));
    return a;
}
__device__ __forceinline__ uint32_t mapa_u32(uint32_t addr, uint32_t rank) {
    uint32_t r;
    asm volatile("mapa.shared::cluster.u32 %0, %1, %2;" : "=r"(r) : "r"(addr), "r"(rank));
    return r;
}
__device__ __forceinline__ uint2 dsmem_ld2(uint32_t addr) {
    uint2 v;
    asm volatile("ld.shared::cluster.v2.u32 {%0, %1}, [%2];"
                 : "=r"(v.x), "=r"(v.y) : "r"(addr));
    return v;
}
__device__ __forceinline__ int dsmem_ld1(uint32_t addr) {
    int v;
    asm volatile("ld.shared::cluster.u32 %0, [%1];" : "=r"(v) : "r"(addr));
    return v;
}
// no-return shared atomic add
__device__ __forceinline__ void red_sh(uint32_t addr, unsigned int val) {
    asm volatile("red.shared.add.u32 [%0], %1;" :: "r"(addr), "r"(val) : "memory");
}
// bin address for quantized value s: base + (s>>1)*4 == base + (s & ~1) * 2
__device__ __forceinline__ uint32_t binAddr(uint32_t base, unsigned int s) {
    return base + ((s & ~1u) << 1);
}

// ---------------------------------------------------------------------------
// Fused kernel: per-quarter histogram + in-cluster DSMEM combine/scan.
// grid = CLU*B, cluster = 4, block = 1024.
// ---------------------------------------------------------------------------
__global__ void __launch_bounds__(TPB, 2) __cluster_dims__(CLU, 1, 1)
k_fused(const float* __restrict__ x, const float* __restrict__ y,
        float* __restrict__ out, int grid) {
    __shared__ unsigned int sh[KB];
    __shared__ int wt[32];
    __shared__ long long wr[32];
    __shared__ int s_segtot;

    int cta = blockIdx.x;
    int b = cta >> 2, q = cta & 3;
    int t = threadIdx.x, lane = t & 31, wid = t >> 5;

    uint4* s4 = (uint4*)sh;
    for (int i = t; i < KB / 4; i += TPB) s4[i] = make_uint4(0u, 0u, 0u, 0u);
    __syncthreads();

    const uint32_t sbase = smem_u32(sh);

    // ---- phase 1: packed signed histogram over this CTA's quarter ----
    // QE/4 = 16384 float4 per stream; 16 iters per thread -> unroll x2 (exact)
    const int QE = HW / CLU;  // 65536 elements each of x, y
    const float4* px = (const float4*)(x + (size_t)b * HW + (size_t)q * QE);
    const float4* py = (const float4*)(y + (size_t)b * HW + (size_t)q * QE);
#pragma unroll 1
    for (int i = t; i < QE / 4; i += 2 * TPB) {
        float4 vx0 = px[i];
        float4 vy0 = py[i];
        float4 vx1 = px[i + TPB];
        float4 vy1 = py[i + TPB];
        unsigned int s;
        s = quantS(vx0.x); red_sh(binAddr(sbase, s), (1u << 22) + s);
        s = quantS(vy0.x); red_sh(binAddr(sbase, s), (unsigned int)(-(int)((1u << 22) + s)));
        s = quantS(vx0.y); red_sh(binAddr(sbase, s), (1u << 22) + s);
        s = quantS(vy0.y); red_sh(binAddr(sbase, s), (unsigned int)(-(int)((1u << 22) + s)));
        s = quantS(vx0.z); red_sh(binAddr(sbase, s), (1u << 22) + s);
        s = quantS(vy0.z); red_sh(binAddr(sbase, s), (unsigned int)(-(int)((1u << 22) + s)));
        s = quantS(vx0.w); red_sh(binAddr(sbase, s), (1u << 22) + s);
        s = quantS(vy0.w); red_sh(binAddr(sbase, s), (unsigned int)(-(int)((1u << 22) + s)));
        s = quantS(vx1.x); red_sh(binAddr(sbase, s), (1u << 22) + s);
        s = quantS(vy1.x); red_sh(binAddr(sbase, s), (unsigned int)(-(int)((1u << 22) + s)));
        s = quantS(vx1.y); red_sh(binAddr(sbase, s), (1u << 22) + s);
        s = quantS(vy1.y); red_sh(binAddr(sbase, s), (unsigned int)(-(int)((1u << 22) + s)));
        s = quantS(vx1.z); red_sh(binAddr(sbase, s), (1u << 22) + s);
        s = quantS(vy1.z); red_sh(binAddr(sbase, s), (unsigned int)(-(int)((1u << 22) + s)));
        s = quantS(vx1.w); red_sh(binAddr(sbase, s), (1u << 22) + s);
        s = quantS(vy1.w); red_sh(binAddr(sbase, s), (unsigned int)(-(int)((1u << 22) + s)));
    }
    __syncthreads();

    // ---- cluster sync #1: all 4 histograms of this batch are complete ----
    asm volatile("barrier.cluster.arrive.aligned;" ::: "memory");
    asm volatile("barrier.cluster.wait.aligned;" ::: "memory");

    // ---- phase 2: combine my 2048-bin segment across the 4 peers (DSMEM) ----
    // thread t handles bins k0 = q*SEG + 2*t, k0+1
    uint32_t myaddr = sbase + (uint32_t)(q * SEG + 2 * t) * 4u;
    unsigned int T0 = 0u, T1 = 0u;
#pragma unroll
    for (int r = 0; r < CLU; ++r) {
        uint2 v = dsmem_ld2(mapa_u32(myaddr, (uint32_t)r));
        T0 += v.x;
        T1 += v.y;
    }
    int d0 = decD(T0), d1 = decD(T1);
    int S0 = (int)T0 - (d0 << 22);
    int S1 = (int)T1 - (d1 << 22);
    int tsum = d0 + d1;

    // block exclusive scan of tsum over 1024 threads
    int s = tsum;
#pragma unroll
    for (int o = 1; o < 32; o <<= 1) {
        int u = __shfl_up_sync(0xffffffffu, s, o);
        if (lane >= o) s += u;
    }
    if (lane == 31) wt[wid] = s;
    __syncthreads();
    if (wid == 0) {
        int w = wt[lane];
#pragma unroll
        for (int o = 1; o < 32; o <<= 1) {
            int u = __shfl_up_sync(0xffffffffu, w, o);
            if (lane >= o) w += u;
        }
        wt[lane] = w;
    }
    __syncthreads();
    int excl = (wid ? wt[wid - 1] : 0) + (s - tsum);
    if (t == 0) s_segtot = wt[31];   // my segment's total d
    __syncthreads();

    // ---- cluster sync #2: segment totals visible cluster-wide ----
    asm volatile("barrier.cluster.arrive.aligned;" ::: "memory");
    asm volatile("barrier.cluster.wait.aligned;" ::: "memory");

    // carry into my segment = sum of earlier segments' totals
    uint32_t segaddr = smem_u32(&s_segtot);
    int carry = 0;
#pragma unroll
    for (int r = 0; r < CLU; ++r)
        if (r < q) carry += dsmem_ld1(mapa_u32(segaddr, (uint32_t)r));

    long long Din = (long long)carry + excl;
    int k0 = q * SEG + 2 * t;  // global bin index of first of my 2 bins

    // exact per-bin integral: 2^15 * integ_k = 4*Din + d_k*(4k+3) - 2*S_k
    long long acc, v;
    v = 4 * Din + (long long)d0 * (4LL * k0 + 3) - 2LL * S0;
    acc = v < 0 ? -v : v;
    Din += d0;
    v = 4 * Din + (long long)d1 * (4LL * k0 + 7) - 2LL * S1;
    acc += v < 0 ? -v : v;

    // block reduce acc (int64)
#pragma unroll
    for (int o = 16; o; o >>= 1) acc += __shfl_down_sync(0xffffffffu, acc, o);
    if (lane == 0) wr[wid] = acc;
    __syncthreads();
    if (wid == 0) {
        acc = wr[lane];
#pragma unroll
        for (int o = 16; o; o >>= 1) acc += __shfl_down_sync(0xffffffffu, acc, o);
        if (lane == 0) {
            atomicAdd(&g_accum, (unsigned long long)acc);
            int r2 = atomicAdd(&g_done, 1);
            if (r2 == grid - 1) {
                unsigned long long tot = atomicAdd(&g_accum, 0ull);
                out[0] = (float)((double)(long long)tot * (1.0 / 32768.0));
                g_accum = 0ull;  // reset for next graph replay
                g_done = 0;
            }
        }
    }
}

extern "C" void kernel_launch(void* const* d_in, const int* in_sizes, int n_in,
                              void* d_out, int out_size) {
    const float* x = (const float*)d_in[0];
    const float* y = (const float*)d_in[1];
    int B = in_sizes[0] / HW;
    if (B > MAXB) B = MAXB;
    int grid = CLU * B;

    k_fused<<<grid, TPB>>>(x, y, (float*)d_out, grid);
}

// round 12
// speedup vs baseline: 1.2930x; 1.0010x over previous
#include <cuda_runtime.h>
#include <cstdint>

#define KB    8192           // bins (bin = S>>1, S = round(v*2^14))
#define SEG   2048           // bins per CTA in phase 2 (KB / CLUSTER)
#define CLU   4              // CTAs per batch = cluster size
#define HW    262144         // H*W per batch
#define MAXB  64
#define TPB   1024

// scratch (allocation-free rule: __device__ globals; zero-initialized)
__device__ unsigned long long g_accum;   // exact integer total
__device__ int                g_done;    // finished-CTA counter

// packed word: T = d*2^22 + S,  S = sum(+-round(v*2^14)) clamped to [0,16383]
__device__ __forceinline__ int decD(unsigned int t) {
    return ((int)t + (1 << 21)) >> 22;
}
__device__ __forceinline__ unsigned int quantS(float v) {
    int S = __float2int_rn(v * 16384.0f);
    return (unsigned int)min(S, 16383);
}

__device__ __forceinline__ uint32_t smem_u32(const void* p) {
    uint32_t a;
    asm("{ .reg .u64 t; cvta.to.shared.u64 t, %1; cvt.u32.u64 %0, t; }" : "=r"(a) : "l"(p));
    return a;
}
__device__ __forceinline__ uint32_t mapa_u32(uint32_t addr, uint32_t rank) {
    uint32_t r;
    asm volatile("mapa.shared::cluster.u32 %0, %1, %2;" : "=r"(r) : "r"(addr), "r"(rank));
    return r;
}
__device__ __forceinline__ uint2 dsmem_ld2(uint32_t addr) {
    uint2 v;
    asm volatile("ld.shared::cluster.v2.u32 {%0, %1}, [%2];"
                 : "=r"(v.x), "=r"(v.y) : "r"(addr));
    return v;
}
__device__ __forceinline__ int dsmem_ld1(uint32_t addr) {
    int v;
    asm volatile("ld.shared::cluster.u32 %0, [%1];" : "=r"(v) : "r"(addr));
    return v;
}
// no-return shared atomic add
__device__ __forceinline__ void red_sh(uint32_t addr, unsigned int val) {
    asm volatile("red.shared.add.u32 [%0], %1;" :: "r"(addr), "r"(val) : "memory");
}
// streaming (evict-first) float4 load
__device__ __forceinline__ float4 ldcs4(const float4* p) {
    float4 v;
    asm volatile("ld.global.cs.v4.f32 {%0, %1, %2, %3}, [%4];"
                 : "=f"(v.x), "=f"(v.y), "=f"(v.z), "=f"(v.w) : "l"(p));
    return v;
}
// bin address for quantized value s: base + (s>>1)*4 == base + (s & ~1) * 2
__device__ __forceinline__ uint32_t binAddr(uint32_t base, unsigned int s) {
    return base + ((s & ~1u) << 1);
}

// ---------------------------------------------------------------------------
// Fused kernel: per-quarter histogram + in-cluster DSMEM combine/scan.
// grid = CLU*B, cluster = 4, block = 1024.
// ---------------------------------------------------------------------------
__global__ void __launch_bounds__(TPB, 2) __cluster_dims__(CLU, 1, 1)
k_fused(const float* __restrict__ x, const float* __restrict__ y,
        float* __restrict__ out, int grid) {
    __shared__ unsigned int sh[KB];
    __shared__ int wt[32];
    __shared__ long long wr[32];
    __shared__ int s_segtot;

    int cta = blockIdx.x;
    int b = cta >> 2, q = cta & 3;
    int t = threadIdx.x, lane = t & 31, wid = t >> 5;

    uint4* s4 = (uint4*)sh;
    for (int i = t; i < KB / 4; i += TPB) s4[i] = make_uint4(0u, 0u, 0u, 0u);
    __syncthreads();

    const uint32_t sbase = smem_u32(sh);

    // ---- phase 1: packed signed histogram over this CTA's quarter ----
    // QE/4 = 16384 float4 per stream; 16 iters per thread -> unroll x2 (exact)
    const int QE = HW / CLU;  // 65536 elements each of x, y
    const float4* px = (const float4*)(x + (size_t)b * HW + (size_t)q * QE);
    const float4* py = (const float4*)(y + (size_t)b * HW + (size_t)q * QE);
#pragma unroll 1
    for (int i = t; i < QE / 4; i += 2 * TPB) {
        // front-batch all four streaming loads (MLP before the ATOMS burst)
        float4 vx0 = ldcs4(px + i);
        float4 vy0 = ldcs4(py + i);
        float4 vx1 = ldcs4(px + i + TPB);
        float4 vy1 = ldcs4(py + i + TPB);
        unsigned int s;
        s = quantS(vx0.x); red_sh(binAddr(sbase, s), (1u << 22) + s);
        s = quantS(vy0.x); red_sh(binAddr(sbase, s), 0xFFC00000u - s);
        s = quantS(vx0.y); red_sh(binAddr(sbase, s), (1u << 22) + s);
        s = quantS(vy0.y); red_sh(binAddr(sbase, s), 0xFFC00000u - s);
        s = quantS(vx0.z); red_sh(binAddr(sbase, s), (1u << 22) + s);
        s = quantS(vy0.z); red_sh(binAddr(sbase, s), 0xFFC00000u - s);
        s = quantS(vx0.w); red_sh(binAddr(sbase, s), (1u << 22) + s);
        s = quantS(vy0.w); red_sh(binAddr(sbase, s), 0xFFC00000u - s);
        s = quantS(vx1.x); red_sh(binAddr(sbase, s), (1u << 22) + s);
        s = quantS(vy1.x); red_sh(binAddr(sbase, s), 0xFFC00000u - s);
        s = quantS(vx1.y); red_sh(binAddr(sbase, s), (1u << 22) + s);
        s = quantS(vy1.y); red_sh(binAddr(sbase, s), 0xFFC00000u - s);
        s = quantS(vx1.z); red_sh(binAddr(sbase, s), (1u << 22) + s);
        s = quantS(vy1.z); red_sh(binAddr(sbase, s), 0xFFC00000u - s);
        s = quantS(vx1.w); red_sh(binAddr(sbase, s), (1u << 22) + s);
        s = quantS(vy1.w); red_sh(binAddr(sbase, s), 0xFFC00000u - s);
    }
    __syncthreads();

    // ---- cluster sync #1: all 4 histograms of this batch are complete ----
    asm volatile("barrier.cluster.arrive.aligned;" ::: "memory");
    asm volatile("barrier.cluster.wait.aligned;" ::: "memory");

    // ---- phase 2: combine my 2048-bin segment across the 4 peers (DSMEM) ----
    // thread t handles bins k0 = q*SEG + 2*t, k0+1
    uint32_t myaddr = sbase + (uint32_t)(q * SEG + 2 * t) * 4u;
    unsigned int T0 = 0u, T1 = 0u;
#pragma unroll
    for (int r = 0; r < CLU; ++r) {
        uint2 v = dsmem_ld2(mapa_u32(myaddr, (uint32_t)r));
        T0 += v.x;
        T1 += v.y;
    }
    int d0 = decD(T0), d1 = decD(T1);
    int S0 = (int)T0 - (d0 << 22);
    int S1 = (int)T1 - (d1 << 22);
    int tsum = d0 + d1;

    // block exclusive scan of tsum over 1024 threads
    int s = tsum;
#pragma unroll
    for (int o = 1; o < 32; o <<= 1) {
        int u = __shfl_up_sync(0xffffffffu, s, o);
        if (lane >= o) s += u;
    }
    if (lane == 31) wt[wid] = s;
    __syncthreads();
    if (wid == 0) {
        int w = wt[lane];
#pragma unroll
        for (int o = 1; o < 32; o <<= 1) {
            int u = __shfl_up_sync(0xffffffffu, w, o);
            if (lane >= o) w += u;
        }
        wt[lane] = w;
    }
    __syncthreads();
    int excl = (wid ? wt[wid - 1] : 0) + (s - tsum);
    if (t == 0) s_segtot = wt[31];   // my segment's total d
    __syncthreads();

    // ---- cluster sync #2: segment totals visible cluster-wide ----
    asm volatile("barrier.cluster.arrive.aligned;" ::: "memory");
    asm volatile("barrier.cluster.wait.aligned;" ::: "memory");

    // carry into my segment = sum of earlier segments' totals
    uint32_t segaddr = smem_u32(&s_segtot);
    int carry = 0;
#pragma unroll
    for (int r = 0; r < CLU; ++r)
        if (r < q) carry += dsmem_ld1(mapa_u32(segaddr, (uint32_t)r));

    long long Din = (long long)carry + excl;
    int k0 = q * SEG + 2 * t;  // global bin index of first of my 2 bins

    // exact per-bin integral: 2^15 * integ_k = 4*Din + d_k*(4k+3) - 2*S_k
    long long acc, v;
    v = 4 * Din + (long long)d0 * (4LL * k0 + 3) - 2LL * S0;
    acc = v < 0 ? -v : v;
    Din += d0;
    v = 4 * Din + (long long)d1 * (4LL * k0 + 7) - 2LL * S1;
    acc += v < 0 ? -v : v;

    // block reduce acc (int64)
#pragma unroll
    for (int o = 16; o; o >>= 1) acc += __shfl_down_sync(0xffffffffu, acc, o);
    if (lane == 0) wr[wid] = acc;
    __syncthreads();
    if (wid == 0) {
        acc = wr[lane];
#pragma unroll
        for (int o = 16; o; o >>= 1) acc += __shfl_down_sync(0xffffffffu, acc, o);
        if (lane == 0) {
            atomicAdd(&g_accum, (unsigned long long)acc);
            int r2 = atomicAdd(&g_done, 1);
            if (r2 == grid - 1) {
                unsigned long long tot = atomicAdd(&g_accum, 0ull);
                out[0] = (float)((double)(long long)tot * (1.0 / 32768.0));
                g_accum = 0ull;  // reset for next graph replay
                g_done = 0;
            }
        }
    }
}

extern "C" void kernel_launch(void* const* d_in, const int* in_sizes, int n_in,
                              void* d_out, int out_size) {
    const float* x = (const float*)d_in[0];
    const float* y = (const float*)d_in[1];
    int B = in_sizes[0] / HW;
    if (B > MAXB) B = MAXB;
    int grid = CLU * B;

    k_fused<<<grid, TPB>>>(x, y, (float*)d_out, grid);
}